// round 3
// baseline (speedup 1.0000x reference)
#include <cuda_runtime.h>
#include <math.h>

#define NN 50000
#define EE 800000

// ---------------- scratch (device globals; no allocation allowed) -----------
__device__ float g_h[(size_t)NN * 256];   // GEMM output / message features
__device__ float g_y[(size_t)NN * 256];   // layer output (post agg/relu/bn)
__device__ float g_as[NN * 4];            // per-node src attention logits
__device__ float g_ad[NN * 4];            // per-node dst attention logits
__device__ int   g_deg[NN];
__device__ int   g_rowptr[NN + 1];
__device__ int   g_cursor[NN];
__device__ int   g_csrc[EE];              // CSR: src node per incoming edge slot
__device__ float g_sums[256];
__device__ float g_sumsq[256];
__device__ float g_scale[256];
__device__ float g_shift[256];
__device__ float g_pool[64 * 64];
__device__ int   g_cnt[64];

// ---------------- CSR build -------------------------------------------------
__global__ void zero_deg_kernel() {
    for (int i = blockIdx.x * blockDim.x + threadIdx.x; i < NN; i += gridDim.x * blockDim.x)
        g_deg[i] = 0;
}

__global__ void count_kernel(const int* __restrict__ dst) {
    for (int e = blockIdx.x * blockDim.x + threadIdx.x; e < EE; e += gridDim.x * blockDim.x)
        atomicAdd(&g_deg[dst[e]], 1);
}

// single-block exclusive scan of g_deg -> g_rowptr, g_cursor
__global__ void scan_kernel() {
    const int T = 1024;
    __shared__ int sh[T];
    int tid = threadIdx.x;
    const int per = (NN + T - 1) / T;  // 49
    int base = tid * per;
    int lim = min(base + per, NN);
    int sum = 0;
    for (int i = base; i < lim; i++) sum += g_deg[i];
    sh[tid] = sum;
    __syncthreads();
    // Hillis-Steele inclusive scan
    for (int off = 1; off < T; off <<= 1) {
        int v = (tid >= off) ? sh[tid - off] : 0;
        __syncthreads();
        sh[tid] += v;
        __syncthreads();
    }
    int run = (tid > 0) ? sh[tid - 1] : 0;
    for (int i = base; i < lim; i++) {
        g_rowptr[i] = run;
        g_cursor[i] = run;
        run += g_deg[i];
    }
    if (tid == T - 1) g_rowptr[NN] = sh[T - 1];
}

__global__ void scatter_kernel(const int* __restrict__ src, const int* __restrict__ dst) {
    for (int e = blockIdx.x * blockDim.x + threadIdx.x; e < EE; e += gridDim.x * blockDim.x) {
        int d = dst[e];
        int pos = atomicAdd(&g_cursor[d], 1);
        g_csrc[pos] = src[e];
    }
}

// ---------------- GEMM: C[M,Nc] = A[M,K] @ B[K,Nc] (fp32) -------------------
// BM=128 BN=64 BK=16, 256 threads, 8x4 microtile.
__global__ void __launch_bounds__(256) gemm_kernel(
    const float* __restrict__ A, const float* __restrict__ B, float* __restrict__ C,
    int M, int K, int Nc)
{
    const int BM = 128, BN = 64, BK = 16;
    __shared__ float sA[BK][BM + 4];
    __shared__ float sB[BK][BN];
    int tid = threadIdx.x;
    int ty = tid >> 4;        // 0..15 -> rows ty*8..ty*8+7
    int tx = tid & 15;        // 0..15 -> cols tx*4..tx*4+3
    int m0 = blockIdx.y * BM;
    int n0 = blockIdx.x * BN;

    float acc[8][4];
#pragma unroll
    for (int i = 0; i < 8; i++)
#pragma unroll
        for (int j = 0; j < 4; j++) acc[i][j] = 0.f;

    for (int k0 = 0; k0 < K; k0 += BK) {
#pragma unroll
        for (int i = tid; i < BM * BK; i += 256) {
            int m = i >> 4, k = i & 15;
            int gm = m0 + m;
            sA[k][m] = (gm < M) ? A[(size_t)gm * K + k0 + k] : 0.f;
        }
#pragma unroll
        for (int i = tid; i < BK * BN; i += 256) {
            int k = i >> 6, c = i & 63;
            sB[k][c] = B[(size_t)(k0 + k) * Nc + n0 + c];
        }
        __syncthreads();
#pragma unroll
        for (int k = 0; k < BK; k++) {
            float4 a0 = *(const float4*)&sA[k][ty * 8];
            float4 a1 = *(const float4*)&sA[k][ty * 8 + 4];
            float4 bv = *(const float4*)&sB[k][tx * 4];
            float av[8] = {a0.x, a0.y, a0.z, a0.w, a1.x, a1.y, a1.z, a1.w};
            float bb[4] = {bv.x, bv.y, bv.z, bv.w};
#pragma unroll
            for (int i = 0; i < 8; i++)
#pragma unroll
                for (int j = 0; j < 4; j++) acc[i][j] += av[i] * bb[j];
        }
        __syncthreads();
    }
#pragma unroll
    for (int i = 0; i < 8; i++) {
        int gm = m0 + ty * 8 + i;
        if (gm < M) {
            float4 v = make_float4(acc[i][0], acc[i][1], acc[i][2], acc[i][3]);
            *(float4*)&C[(size_t)gm * Nc + n0 + tx * 4] = v;
        }
    }
}

// ---------------- per-node attention logits ---------------------------------
template <int H>
__global__ void attn_kernel(const float* __restrict__ h,
                            const float* __restrict__ a_src,
                            const float* __restrict__ a_dst)
{
    int idx = blockIdx.x * blockDim.x + threadIdx.x;
    if (idx >= NN * H) return;
    int n = idx / H, hh = idx % H;
    const float4* row = reinterpret_cast<const float4*>(h + (size_t)n * (H * 64) + hh * 64);
    const float4* av = reinterpret_cast<const float4*>(a_src + hh * 64);
    const float4* dv = reinterpret_cast<const float4*>(a_dst + hh * 64);
    float s = 0.f, d = 0.f;
#pragma unroll
    for (int i = 0; i < 16; i++) {
        float4 r = row[i], a = av[i], b = dv[i];
        s += r.x * a.x + r.y * a.y + r.z * a.z + r.w * a.w;
        d += r.x * b.x + r.y * b.y + r.z * b.z + r.w * b.w;
    }
    g_as[idx] = s;
    g_ad[idx] = d;
}

// ---------------- softmax-weighted gather aggregation (one block per node) --
// out[n, h*64+c] = relu( (sum_e exp(lrelu(as[src_e,h]+ad[n,h])) * hfeat[src_e,h,c])
//                        / (sum_e exp(...)) + bias )
template <int H>
__global__ void __launch_bounds__(H * 64) agg_kernel(
    const float* __restrict__ h, const float* __restrict__ bias, float* __restrict__ out)
{
    const int OUT = H * 64;
    const int CH = 128;
    int n = blockIdx.x;
    int tid = threadIdx.x;
    int myh = tid >> 6;
    int start = g_rowptr[n], end = g_rowptr[n + 1];

    __shared__ float s_ex[CH * H];
    __shared__ int   s_src[CH];
    __shared__ float s_den[H];
    __shared__ float s_ad[H];
    if (tid < H) { s_ad[tid] = g_ad[n * H + tid]; s_den[tid] = 0.f; }
    __syncthreads();

    float acc = 0.f;
    for (int cb = start; cb < end; cb += CH) {
        int clen = min(CH, end - cb);
        for (int i = tid; i < clen; i += OUT) s_src[i] = g_csrc[cb + i];
        __syncthreads();
        for (int i = tid; i < clen * H; i += OUT) {
            int el = i / H, hh = i % H;
            float e = g_as[s_src[el] * H + hh] + s_ad[hh];
            e = (e > 0.f) ? e : 0.2f * e;
            float ex = expf(e);
            s_ex[i] = ex;
            atomicAdd(&s_den[hh], ex);
        }
        __syncthreads();
#pragma unroll 4
        for (int el = 0; el < clen; el++) {
            acc += s_ex[el * H + myh] * h[(size_t)s_src[el] * OUT + tid];
        }
        __syncthreads();
    }
    float v = 0.f;
    if (end > start) v = acc / s_den[myh];
    v += bias[tid];
    out[(size_t)n * OUT + tid] = (v > 0.f) ? v : 0.f;
}

// ---------------- batch norm ------------------------------------------------
__global__ void zero_bn_kernel() {
    int t = threadIdx.x;
    if (t < 256) { g_sums[t] = 0.f; g_sumsq[t] = 0.f; }
}

__global__ void bn_stats_kernel(const float* __restrict__ y, int OUT) {
    int c = threadIdx.x;  // blockDim == OUT
    float s = 0.f, s2 = 0.f;
    for (int r = blockIdx.x; r < NN; r += gridDim.x) {
        float v = y[(size_t)r * OUT + c];
        s += v; s2 += v * v;
    }
    atomicAdd(&g_sums[c], s);
    atomicAdd(&g_sumsq[c], s2);
}

__global__ void bn_final_kernel(const float* __restrict__ g, const float* __restrict__ be, int OUT) {
    int c = threadIdx.x;
    if (c >= OUT) return;
    float mean = g_sums[c] * (1.f / NN);
    float var = g_sumsq[c] * (1.f / NN) - mean * mean;
    float sc = g[c] * rsqrtf(var + 1e-5f);
    g_scale[c] = sc;
    g_shift[c] = be[c] - mean * sc;
}

__global__ void bn_apply_kernel(float* __restrict__ y, int OUT, int total) {
    for (int idx = blockIdx.x * blockDim.x + threadIdx.x; idx < total; idx += gridDim.x * blockDim.x) {
        int c = idx & (OUT - 1);
        y[idx] = y[idx] * g_scale[c] + g_shift[c];
    }
}

// ---------------- global mean pool + classifier -----------------------------
__global__ void zero_pool_kernel() {
    int t = blockIdx.x * blockDim.x + threadIdx.x;
    if (t < 64 * 64) g_pool[t] = 0.f;
    if (t < 64) g_cnt[t] = 0;
}

__global__ void pool_kernel(const float* __restrict__ y, const int* __restrict__ batch) {
    int idx = blockIdx.x * blockDim.x + threadIdx.x;
    if (idx >= NN * 64) return;
    int n = idx >> 6, c = idx & 63;
    int b = batch[n];
    atomicAdd(&g_pool[b * 64 + c], y[idx]);
    if (c == 0) atomicAdd(&g_cnt[b], 1);
}

__global__ void fc_kernel(const float* __restrict__ fcW, const float* __restrict__ fcb,
                          float* __restrict__ out) {
    int idx = threadIdx.x;  // 640
    if (idx >= 640) return;
    int g = idx / 10, k = idx % 10;
    float cnt = (float)g_cnt[g];
    if (cnt < 1.f) cnt = 1.f;
    float s = 0.f;
#pragma unroll
    for (int c = 0; c < 64; c++) s += g_pool[g * 64 + c] * fcW[c * 10 + k];
    out[idx] = s / cnt + fcb[k];
}

// ---------------- driver ----------------------------------------------------
extern "C" void kernel_launch(void* const* d_in, const int* in_sizes, int n_in,
                              void* d_out, int out_size)
{
    const float* x     = (const float*)d_in[0];
    const int*   ei    = (const int*)d_in[1];
    const int*   batch = (const int*)d_in[2];
    const float* W1   = (const float*)d_in[3];
    const float* as1  = (const float*)d_in[4];
    const float* ad1  = (const float*)d_in[5];
    const float* b1   = (const float*)d_in[6];
    const float* gm1  = (const float*)d_in[7];
    const float* be1  = (const float*)d_in[8];
    const float* W2   = (const float*)d_in[9];
    const float* as2  = (const float*)d_in[10];
    const float* ad2  = (const float*)d_in[11];
    const float* b2   = (const float*)d_in[12];
    const float* gm2  = (const float*)d_in[13];
    const float* be2  = (const float*)d_in[14];
    const float* W3   = (const float*)d_in[15];
    const float* as3  = (const float*)d_in[16];
    const float* ad3  = (const float*)d_in[17];
    const float* b3   = (const float*)d_in[18];
    const float* gm3  = (const float*)d_in[19];
    const float* be3  = (const float*)d_in[20];
    const float* fcW  = (const float*)d_in[21];
    const float* fcb  = (const float*)d_in[22];

    const int* src = ei;
    const int* dst = ei + EE;

    float *p_h = nullptr, *p_y = nullptr;
    cudaGetSymbolAddress((void**)&p_h, g_h);
    cudaGetSymbolAddress((void**)&p_y, g_y);

    // ---- CSR build (edge_index is an input, so rebuilt every call) ----
    zero_deg_kernel<<<196, 256>>>();
    count_kernel<<<784, 1024>>>(dst);
    scan_kernel<<<1, 1024>>>();
    scatter_kernel<<<784, 1024>>>(src, dst);

    const int GY = (NN + 127) / 128;

    // ---- layer 1: 128 -> 4x64 concat ----
    gemm_kernel<<<dim3(4, GY), 256>>>(x, W1, p_h, NN, 128, 256);
    attn_kernel<4><<<(NN * 4 + 255) / 256, 256>>>(p_h, as1, ad1);
    agg_kernel<4><<<NN, 256>>>(p_h, b1, p_y);
    zero_bn_kernel<<<1, 256>>>();
    bn_stats_kernel<<<512, 256>>>(p_y, 256);
    bn_final_kernel<<<1, 256>>>(gm1, be1, 256);
    bn_apply_kernel<<<1024, 256>>>(p_y, 256, NN * 256);

    // ---- layer 2: 256 -> 4x64 concat ----
    gemm_kernel<<<dim3(4, GY), 256>>>(p_y, W2, p_h, NN, 256, 256);
    attn_kernel<4><<<(NN * 4 + 255) / 256, 256>>>(p_h, as2, ad2);
    agg_kernel<4><<<NN, 256>>>(p_h, b2, p_y);
    zero_bn_kernel<<<1, 256>>>();
    bn_stats_kernel<<<512, 256>>>(p_y, 256);
    bn_final_kernel<<<1, 256>>>(gm2, be2, 256);
    bn_apply_kernel<<<1024, 256>>>(p_y, 256, NN * 256);

    // ---- layer 3: 256 -> 1x64 ----
    gemm_kernel<<<dim3(1, GY), 256>>>(p_y, W3, p_h, NN, 256, 64);
    attn_kernel<1><<<(NN + 255) / 256, 256>>>(p_h, as3, ad3);
    agg_kernel<1><<<NN, 64>>>(p_h, b3, p_y);
    zero_bn_kernel<<<1, 256>>>();
    bn_stats_kernel<<<512, 64>>>(p_y, 64);
    bn_final_kernel<<<1, 64>>>(gm3, be3, 64);
    bn_apply_kernel<<<1024, 256>>>(p_y, 64, NN * 64);

    // ---- pool + classifier ----
    zero_pool_kernel<<<16, 256>>>();
    pool_kernel<<<(NN * 64 + 255) / 256, 256>>>(p_y, batch);
    fc_kernel<<<1, 640>>>(fcW, fcb, (float*)d_out);
}

// round 5
// speedup vs baseline: 1.0727x; 1.0727x over previous
#include <cuda_runtime.h>
#include <cuda_bf16.h>
#include <math.h>
#include <stdint.h>

#define NN 50000
#define EE 800000

// ---------------- scratch (device globals; no allocation allowed) -----------
__device__ float g_h[(size_t)NN * 256];           // GEMM output (h features)
__device__ float g_y[(size_t)NN * 256];           // agg output (relu'd)
__device__ __nv_bfloat16 g_ah[(size_t)NN * 256];  // A hi split
__device__ __nv_bfloat16 g_al[(size_t)NN * 256];  // A lo split
__device__ __nv_bfloat16 g_wht[256 * 256];        // W'^T hi [Npad][K]
__device__ __nv_bfloat16 g_wlt[256 * 256];        // W'^T lo
__device__ float g_biasp[256];                    // bias' (BN shift @ W)
__device__ float g_as[NN * 4];
__device__ float g_ad[NN * 4];
__device__ int   g_deg[NN];
__device__ int   g_rowptr[NN + 1];
__device__ int   g_cursor[NN];
__device__ int   g_csrc[EE];
__device__ float g_sums[256];
__device__ float g_sumsq[256];
__device__ float g_scale[256];
__device__ float g_shift[256];
__device__ float g_pool[64 * 64];
__device__ int   g_cnt[64];

// ---------------- warp-MMA helpers (family-portable PTX) ----------------------
__device__ __forceinline__ uint32_t smem_u32(const void* p) {
    uint32_t a;
    asm("{ .reg .u64 t; cvta.to.shared.u64 t, %1; cvt.u32.u64 %0, t; }" : "=r"(a) : "l"(p));
    return a;
}
__device__ __forceinline__ void ldmx4(uint32_t addr, uint32_t* r) {
    asm volatile("ldmatrix.sync.aligned.m8n8.x4.shared.b16 {%0,%1,%2,%3}, [%4];"
                 : "=r"(r[0]), "=r"(r[1]), "=r"(r[2]), "=r"(r[3]) : "r"(addr));
}
__device__ __forceinline__ void mma16816(float* d, const uint32_t* a, uint32_t b0, uint32_t b1) {
    asm volatile(
        "mma.sync.aligned.m16n8k16.row.col.f32.bf16.bf16.f32 "
        "{%0,%1,%2,%3}, {%4,%5,%6,%7}, {%8,%9}, {%0,%1,%2,%3};"
        : "+f"(d[0]), "+f"(d[1]), "+f"(d[2]), "+f"(d[3])
        : "r"(a[0]), "r"(a[1]), "r"(a[2]), "r"(a[3]), "r"(b0), "r"(b1));
}

// ---------------- CSR build ---------------------------------------------------
__global__ void zero_deg_kernel() {
    for (int i = blockIdx.x * blockDim.x + threadIdx.x; i < NN; i += gridDim.x * blockDim.x)
        g_deg[i] = 0;
}
__global__ void count_kernel(const int* __restrict__ dst) {
    for (int e = blockIdx.x * blockDim.x + threadIdx.x; e < EE; e += gridDim.x * blockDim.x)
        atomicAdd(&g_deg[dst[e]], 1);
}
__global__ void scan_kernel() {
    const int T = 1024;
    __shared__ int sh[T];
    int tid = threadIdx.x;
    const int per = (NN + T - 1) / T;
    int base = tid * per;
    int lim = min(base + per, NN);
    int sum = 0;
    for (int i = base; i < lim; i++) sum += g_deg[i];
    sh[tid] = sum;
    __syncthreads();
    for (int off = 1; off < T; off <<= 1) {
        int v = (tid >= off) ? sh[tid - off] : 0;
        __syncthreads();
        sh[tid] += v;
        __syncthreads();
    }
    int run = (tid > 0) ? sh[tid - 1] : 0;
    for (int i = base; i < lim; i++) {
        g_rowptr[i] = run;
        g_cursor[i] = run;
        run += g_deg[i];
    }
    if (tid == T - 1) g_rowptr[NN] = sh[T - 1];
}
__global__ void scatter_kernel(const int* __restrict__ src, const int* __restrict__ dst) {
    for (int e = blockIdx.x * blockDim.x + threadIdx.x; e < EE; e += gridDim.x * blockDim.x) {
        int d = dst[e];
        int pos = atomicAdd(&g_cursor[d], 1);
        g_csrc[pos] = src[e];
    }
}

// ---------------- input / weight prep -----------------------------------------
__global__ void convx_kernel(const float* __restrict__ x) {
    int i = blockIdx.x * blockDim.x + threadIdx.x;
    if (i >= NN * 128) return;
    float v = x[i];
    __nv_bfloat16 h = __float2bfloat16(v);
    g_ah[i] = h;
    g_al[i] = __float2bfloat16(v - __bfloat162float(h));
}

// W'[k][n] = scale[k]*W[k][n] (or W); write transposed [Npad][K] hi/lo
__global__ void wprep_kernel(const float* __restrict__ W, int K, int Nreal, int Npad, int useBN) {
    int idx = blockIdx.x * blockDim.x + threadIdx.x;
    if (idx >= Npad * K) return;
    int n = idx / K, k = idx % K;
    float v = 0.f;
    if (n < Nreal) {
        float sc = useBN ? g_scale[k] : 1.f;
        v = sc * W[(size_t)k * Nreal + n];
    }
    __nv_bfloat16 h = __float2bfloat16(v);
    g_wht[idx] = h;
    g_wlt[idx] = __float2bfloat16(v - __bfloat162float(h));
}

// bias'[n] = sum_k shift[k] * W[k][n]
__global__ void bprep_kernel(const float* __restrict__ W, int K, int Nreal, int Npad, int useBN) {
    int n = blockIdx.x * blockDim.x + threadIdx.x;
    if (n >= Npad) return;
    float s = 0.f;
    if (useBN && n < Nreal)
        for (int k = 0; k < K; k++) s += g_shift[k] * W[(size_t)k * Nreal + n];
    g_biasp[n] = s;
}

// ---------------- split-bf16 HMMA GEMM + fused attn-logit epilogue -------------
// C[128x128 tile] = (Ah+Al)[128,K] @ (Bh+Bl)^T ; fp32 accumulate.
// Block: 256 threads = 8 warps (4 m x 2 n); warp tile 32x64.
template <int KDIM, int H, int NSTORE>
__global__ void __launch_bounds__(256) gemm_mma_kernel(
    const float* __restrict__ a_srcv, const float* __restrict__ a_dstv)
{
    // smem tiles: 128 rows x 16 k (bf16), row stride 24 elems (48B, ldmatrix conflict-free)
    __shared__ __nv_bfloat16 sAh[128 * 24], sAl[128 * 24];
    __shared__ __nv_bfloat16 sBh[128 * 24], sBl[128 * 24];
    __shared__ float s_av_s[128], s_av_d[128], s_bias[128];
    __shared__ float s_pas[2][128], s_pad[2][128];

    const int tid = threadIdx.x;
    const int wid = tid >> 5, lane = tid & 31;
    const int warp_m = wid & 3, warp_n = wid >> 2;
    const int m0 = blockIdx.y * 128, n0 = blockIdx.x * 128;

    if (tid < 128) {
        int c = n0 + tid;
        float avs = 0.f, avd = 0.f;
        if (c < H * 64) { avs = a_srcv[c]; avd = a_dstv[c]; }
        s_av_s[tid] = avs;
        s_av_d[tid] = avd;
        s_bias[tid] = g_biasp[c];
        s_pas[0][tid] = 0.f; s_pas[1][tid] = 0.f;
        s_pad[0][tid] = 0.f; s_pad[1][tid] = 0.f;
    }

    float acc[2][8][4];
#pragma unroll
    for (int i = 0; i < 2; i++)
#pragma unroll
        for (int j = 0; j < 8; j++)
#pragma unroll
            for (int q = 0; q < 4; q++) acc[i][j][q] = 0.f;

    const int row_ld = tid >> 1;          // 0..127
    const int seg = tid & 1;              // 0..1 (8 bf16 each)
    const int l8 = lane & 7, sel = lane >> 3;

    const int NCH = KDIM / 16;
    for (int ch = 0; ch < NCH; ch++) {
        __syncthreads();
        const int k0 = ch * 16;
        // ---- A tile (row-guarded) ----
        {
            int gm = m0 + row_ld;
            size_t ga = (size_t)gm * KDIM + k0 + seg * 8;
            uint4 vh = make_uint4(0, 0, 0, 0), vl = make_uint4(0, 0, 0, 0);
            if (gm < NN) {
                vh = *(const uint4*)(g_ah + ga);
                vl = *(const uint4*)(g_al + ga);
            }
            *(uint4*)&sAh[row_ld * 24 + seg * 8] = vh;
            *(uint4*)&sAl[row_ld * 24 + seg * 8] = vl;
        }
        // ---- B tile (Npad rows always valid) ----
        {
            size_t gb = (size_t)(n0 + row_ld) * KDIM + k0 + seg * 8;
            *(uint4*)&sBh[row_ld * 24 + seg * 8] = *(const uint4*)(g_wht + gb);
            *(uint4*)&sBl[row_ld * 24 + seg * 8] = *(const uint4*)(g_wlt + gb);
        }
        __syncthreads();

        // ---- A fragments (2 m-tiles, hi+lo) ----
        uint32_t ah[2][4], al[2][4];
#pragma unroll
        for (int mf = 0; mf < 2; mf++) {
            int row = warp_m * 32 + mf * 16 + l8 + ((sel & 1) << 3);
            int kof = (sel >> 1) << 3;
            ldmx4(smem_u32(&sAh[row * 24 + kof]), ah[mf]);
            ldmx4(smem_u32(&sAl[row * 24 + kof]), al[mf]);
        }
        // ---- B fragments (pairs of n-tiles) + MMA ----
#pragma unroll
        for (int nf2 = 0; nf2 < 4; nf2++) {
            int nrow = warp_n * 64 + nf2 * 16 + l8 + ((sel >> 1) << 3);
            int kof = (sel & 1) << 3;
            uint32_t bh[4], bl[4];
            ldmx4(smem_u32(&sBh[nrow * 24 + kof]), bh);
            ldmx4(smem_u32(&sBl[nrow * 24 + kof]), bl);
#pragma unroll
            for (int mf = 0; mf < 2; mf++) {
                mma16816(acc[mf][nf2 * 2],     ah[mf], bh[0], bh[1]);
                mma16816(acc[mf][nf2 * 2],     ah[mf], bl[0], bl[1]);
                mma16816(acc[mf][nf2 * 2],     al[mf], bh[0], bh[1]);
                mma16816(acc[mf][nf2 * 2 + 1], ah[mf], bh[2], bh[3]);
                mma16816(acc[mf][nf2 * 2 + 1], ah[mf], bl[2], bl[3]);
                mma16816(acc[mf][nf2 * 2 + 1], al[mf], bh[2], bh[3]);
            }
        }
    }
    __syncthreads();

    // ---- epilogue: +bias', attn dots, store h ----
    const int r_q = warp_m * 32 + (lane >> 2);
#pragma unroll
    for (int mf = 0; mf < 2; mf++) {
        int r_lo = r_q + mf * 16;
        int gm_lo = m0 + r_lo, gm_hi = gm_lo + 8;
        float as_lo = 0.f, as_hi = 0.f, ad_lo = 0.f, ad_hi = 0.f;
#pragma unroll
        for (int nf = 0; nf < 8; nf++) {
            int cl = warp_n * 64 + nf * 8 + ((lane & 3) << 1);
            float b0 = s_bias[cl], b1 = s_bias[cl + 1];
            float v0 = acc[mf][nf][0] + b0;
            float v1 = acc[mf][nf][1] + b1;
            float v2 = acc[mf][nf][2] + b0;
            float v3 = acc[mf][nf][3] + b1;
            float a0 = s_av_s[cl], a1 = s_av_s[cl + 1];
            float d0 = s_av_d[cl], d1 = s_av_d[cl + 1];
            as_lo += v0 * a0 + v1 * a1;
            as_hi += v2 * a0 + v3 * a1;
            ad_lo += v0 * d0 + v1 * d1;
            ad_hi += v2 * d0 + v3 * d1;
            int gc = n0 + cl;
            if (gc < NSTORE) {
                if (gm_lo < NN) *(float2*)&g_h[(size_t)gm_lo * NSTORE + gc] = make_float2(v0, v1);
                if (gm_hi < NN) *(float2*)&g_h[(size_t)gm_hi * NSTORE + gc] = make_float2(v2, v3);
            }
        }
        atomicAdd(&s_pas[warp_n][r_lo], as_lo);
        atomicAdd(&s_pas[warp_n][r_lo + 8], as_hi);
        atomicAdd(&s_pad[warp_n][r_lo], ad_lo);
        atomicAdd(&s_pad[warp_n][r_lo + 8], ad_hi);
    }
    __syncthreads();
    if (tid < 128) {
        int gm = m0 + tid;
        if (gm < NN) {
            int hb = n0 >> 6;
#pragma unroll
            for (int lh = 0; lh < 2; lh++) {
                int head = hb + lh;
                if (head < H) {
                    g_as[gm * H + head] = s_pas[lh][tid];
                    g_ad[gm * H + head] = s_pad[lh][tid];
                }
            }
        }
    }
}

// ---------------- softmax-weighted gather aggregation --------------------------
template <int H, bool WB>
__global__ void __launch_bounds__(H * 64) agg_kernel(
    const float* __restrict__ h, const float* __restrict__ bias, float* __restrict__ out)
{
    const int OUT = H * 64;
    const int CH = 128;
    int n = blockIdx.x;
    int tid = threadIdx.x;
    int myh = tid >> 6;
    int start = g_rowptr[n], end = g_rowptr[n + 1];

    __shared__ float s_ex[CH * H];
    __shared__ int   s_src[CH];
    __shared__ float s_den[H];
    __shared__ float s_ad[H];
    if (tid < H) { s_ad[tid] = g_ad[n * H + tid]; s_den[tid] = 0.f; }
    __syncthreads();

    float acc = 0.f;
    for (int cb = start; cb < end; cb += CH) {
        int clen = min(CH, end - cb);
        for (int i = tid; i < clen; i += OUT) s_src[i] = g_csrc[cb + i];
        __syncthreads();
        for (int i = tid; i < clen * H; i += OUT) {
            int el = i / H, hh = i % H;
            float e = g_as[s_src[el] * H + hh] + s_ad[hh];
            e = (e > 0.f) ? e : 0.2f * e;
            float ex = expf(e);
            s_ex[i] = ex;
            atomicAdd(&s_den[hh], ex);
        }
        __syncthreads();
#pragma unroll 4
        for (int el = 0; el < clen; el++) {
            acc += s_ex[el * H + myh] * h[(size_t)s_src[el] * OUT + tid];
        }
        __syncthreads();
    }
    float v = 0.f;
    if (end > start) v = acc / s_den[myh];
    v += bias[tid];
    v = (v > 0.f) ? v : 0.f;
    size_t idx = (size_t)n * OUT + tid;
    out[idx] = v;
    if (WB) {
        __nv_bfloat16 hv = __float2bfloat16(v);
        g_ah[idx] = hv;
        g_al[idx] = __float2bfloat16(v - __bfloat162float(hv));
    }
}

// ---------------- batch norm stats (apply folded into next-layer weights) -----
__global__ void zero_bn_kernel() {
    int t = threadIdx.x;
    if (t < 256) { g_sums[t] = 0.f; g_sumsq[t] = 0.f; }
}
__global__ void bn_stats_kernel(const float* __restrict__ y, int OUT) {
    int c = threadIdx.x;
    float s = 0.f, s2 = 0.f;
    for (int r = blockIdx.x; r < NN; r += gridDim.x) {
        float v = y[(size_t)r * OUT + c];
        s += v; s2 += v * v;
    }
    atomicAdd(&g_sums[c], s);
    atomicAdd(&g_sumsq[c], s2);
}
__global__ void bn_final_kernel(const float* __restrict__ g, const float* __restrict__ be, int OUT) {
    int c = threadIdx.x;
    if (c >= OUT) return;
    float mean = g_sums[c] * (1.f / NN);
    float var = g_sumsq[c] * (1.f / NN) - mean * mean;
    float sc = g[c] * rsqrtf(var + 1e-5f);
    g_scale[c] = sc;
    g_shift[c] = be[c] - mean * sc;
}

// ---------------- pool + classifier (BN3 folded in) ----------------------------
__global__ void zero_pool_kernel() {
    int t = blockIdx.x * blockDim.x + threadIdx.x;
    if (t < 64 * 64) g_pool[t] = 0.f;
    if (t < 64) g_cnt[t] = 0;
}
__global__ void pool_kernel(const float* __restrict__ y, const int* __restrict__ batch) {
    int idx = blockIdx.x * blockDim.x + threadIdx.x;
    if (idx >= NN * 64) return;
    int n = idx >> 6, c = idx & 63;
    int b = batch[n];
    atomicAdd(&g_pool[b * 64 + c], y[idx]);
    if (c == 0) atomicAdd(&g_cnt[b], 1);
}
__global__ void fc_kernel(const float* __restrict__ fcW, const float* __restrict__ fcb,
                          float* __restrict__ out) {
    int idx = threadIdx.x;
    if (idx >= 640) return;
    int g = idx / 10, k = idx % 10;
    float cnt = (float)g_cnt[g];
    if (cnt < 1.f) cnt = 1.f;
    float inv = 1.f / cnt;
    float s = 0.f;
#pragma unroll
    for (int c = 0; c < 64; c++) {
        float pooled = g_pool[g * 64 + c] * inv;
        float bn = pooled * g_scale[c] + g_shift[c];
        s += bn * fcW[c * 10 + k];
    }
    out[idx] = s + fcb[k];
}

// ---------------- driver --------------------------------------------------------
extern "C" void kernel_launch(void* const* d_in, const int* in_sizes, int n_in,
                              void* d_out, int out_size)
{
    const float* x     = (const float*)d_in[0];
    const int*   ei    = (const int*)d_in[1];
    const int*   batch = (const int*)d_in[2];
    const float* W1   = (const float*)d_in[3];
    const float* as1  = (const float*)d_in[4];
    const float* ad1  = (const float*)d_in[5];
    const float* b1   = (const float*)d_in[6];
    const float* gm1  = (const float*)d_in[7];
    const float* be1  = (const float*)d_in[8];
    const float* W2   = (const float*)d_in[9];
    const float* as2  = (const float*)d_in[10];
    const float* ad2  = (const float*)d_in[11];
    const float* b2   = (const float*)d_in[12];
    const float* gm2  = (const float*)d_in[13];
    const float* be2  = (const float*)d_in[14];
    const float* W3   = (const float*)d_in[15];
    const float* as3  = (const float*)d_in[16];
    const float* ad3  = (const float*)d_in[17];
    const float* b3   = (const float*)d_in[18];
    const float* gm3  = (const float*)d_in[19];
    const float* be3  = (const float*)d_in[20];
    const float* fcW  = (const float*)d_in[21];
    const float* fcb  = (const float*)d_in[22];

    const int* src = ei;
    const int* dst = ei + EE;

    float *p_h = nullptr, *p_y = nullptr;
    cudaGetSymbolAddress((void**)&p_h, g_h);
    cudaGetSymbolAddress((void**)&p_y, g_y);

    // ---- CSR build ----
    zero_deg_kernel<<<196, 256>>>();
    count_kernel<<<784, 1024>>>(dst);
    scan_kernel<<<1, 1024>>>();
    scatter_kernel<<<784, 1024>>>(src, dst);

    const int GY = (NN + 127) / 128;  // 391

    // ---- layer 1: 128 -> 4x64 concat ----
    convx_kernel<<<(NN * 128 + 255) / 256, 256>>>(x);
    wprep_kernel<<<(256 * 128 + 255) / 256, 256>>>(W1, 128, 256, 256, 0);
    bprep_kernel<<<1, 256>>>(W1, 128, 256, 256, 0);
    gemm_mma_kernel<128, 4, 256><<<dim3(2, GY), 256>>>(as1, ad1);
    agg_kernel<4, true><<<NN, 256>>>(p_h, b1, p_y);
    zero_bn_kernel<<<1, 256>>>();
    bn_stats_kernel<<<512, 256>>>(p_y, 256);
    bn_final_kernel<<<1, 256>>>(gm1, be1, 256);

    // ---- layer 2: 256 -> 4x64 concat (BN1 folded into W2) ----
    wprep_kernel<<<(256 * 256 + 255) / 256, 256>>>(W2, 256, 256, 256, 1);
    bprep_kernel<<<1, 256>>>(W2, 256, 256, 256, 1);
    gemm_mma_kernel<256, 4, 256><<<dim3(2, GY), 256>>>(as2, ad2);
    agg_kernel<4, true><<<NN, 256>>>(p_h, b2, p_y);
    zero_bn_kernel<<<1, 256>>>();
    bn_stats_kernel<<<512, 256>>>(p_y, 256);
    bn_final_kernel<<<1, 256>>>(gm2, be2, 256);

    // ---- layer 3: 256 -> 1x64 (BN2 folded into W3; N padded to 128) ----
    wprep_kernel<<<(128 * 256 + 255) / 256, 256>>>(W3, 256, 64, 128, 1);
    bprep_kernel<<<1, 128>>>(W3, 256, 64, 128, 1);
    gemm_mma_kernel<256, 1, 64><<<dim3(1, GY), 256>>>(as3, ad3);
    agg_kernel<1, false><<<NN, 64>>>(p_h, b3, p_y);
    zero_bn_kernel<<<1, 256>>>();
    bn_stats_kernel<<<512, 64>>>(p_y, 64);
    bn_final_kernel<<<1, 64>>>(gm3, be3, 64);

    // ---- pool + classifier (BN3 applied affinely post-pool) ----
    zero_pool_kernel<<<16, 256>>>();
    pool_kernel<<<(NN * 64 + 255) / 256, 256>>>(p_y, batch);
    fc_kernel<<<1, 640>>>(fcW, fcb, (float*)d_out);
}